// round 4
// baseline (speedup 1.0000x reference)
#include <cuda_runtime.h>

// ---------------------------------------------------------------------------
// Multi-head attention: y -> Q,K,V proj -> softmax(QK^T/sqrt(d))V -> out proj
// B=2, N=2048, D_MODEL=1024, H=16, D_K=D_V=64.  All fp32 SIMT this round.
// ---------------------------------------------------------------------------

namespace {
constexpr int Bb = 2;
constexpr int Nn = 2048;
constexpr int DM = 1024;   // d_model
constexpr int Hh = 16;
constexpr int Dh = 64;     // head dim
constexpr int Mrows = Bb * Nn;          // 4096 token rows
constexpr int QTILE = 64;               // queries per attention block
constexpr int KTILE = 64;               // keys per inner tile
}

// Scratch: Q,K,V,O in (b, n, h, d) layout = [Mrows][DM] row-major. 16 MB each.
__device__ float g_Q[Mrows * DM];
__device__ float g_K[Mrows * DM];
__device__ float g_V[Mrows * DM];
__device__ float g_O[Mrows * DM];

// ---------------------------------------------------------------------------
// GEMM body: C[m][n] = sum_k A[m][k] * W[n][k] + bias[n]
// A: [4096][1024] row-major (k contiguous), W: [1024][1024] row-major
// (k contiguous).  Block tile 128x128, K-tile 16, 256 threads, 8x8 per thread.
// ---------------------------------------------------------------------------
__device__ __forceinline__ void gemm_body(
    const float* __restrict__ A, const float* __restrict__ W,
    const float* __restrict__ bias, float* __restrict__ C)
{
    constexpr int K = DM;      // 1024
    constexpr int Ncols = DM;  // 1024

    __shared__ __align__(16) float As[16][128];  // [k][m]
    __shared__ __align__(16) float Bs[16][128];  // [k][n]

    const int tid = threadIdx.x;
    const int tx = tid & 15;    // n-group
    const int ty = tid >> 4;    // m-group
    const int rowBase = blockIdx.y * 128;
    const int colBase = blockIdx.x * 128;

    float acc[8][8];
#pragma unroll
    for (int i = 0; i < 8; i++)
#pragma unroll
        for (int j = 0; j < 8; j++) acc[i][j] = 0.0f;

    for (int k0 = 0; k0 < K; k0 += 16) {
        // Load 128x16 tiles of A and W, transposed into [k][row] smem.
        // 512 float4 each; 2 per thread per operand.
#pragma unroll
        for (int i = 0; i < 2; i++) {
            int f = tid + i * 256;
            int r = f >> 2;             // row within tile (0..127)
            int kc = (f & 3) << 2;      // k offset within tile (0,4,8,12)
            float4 va = *reinterpret_cast<const float4*>(
                A + (rowBase + r) * K + k0 + kc);
            As[kc + 0][r] = va.x; As[kc + 1][r] = va.y;
            As[kc + 2][r] = va.z; As[kc + 3][r] = va.w;
            float4 vb = *reinterpret_cast<const float4*>(
                W + (colBase + r) * K + k0 + kc);
            Bs[kc + 0][r] = vb.x; Bs[kc + 1][r] = vb.y;
            Bs[kc + 2][r] = vb.z; Bs[kc + 3][r] = vb.w;
        }
        __syncthreads();

#pragma unroll
        for (int k = 0; k < 16; k++) {
            float a[8], b[8];
            *reinterpret_cast<float4*>(&a[0]) =
                *reinterpret_cast<const float4*>(&As[k][ty * 8]);
            *reinterpret_cast<float4*>(&a[4]) =
                *reinterpret_cast<const float4*>(&As[k][ty * 8 + 4]);
            *reinterpret_cast<float4*>(&b[0]) =
                *reinterpret_cast<const float4*>(&Bs[k][tx * 8]);
            *reinterpret_cast<float4*>(&b[4]) =
                *reinterpret_cast<const float4*>(&Bs[k][tx * 8 + 4]);
#pragma unroll
            for (int i = 0; i < 8; i++)
#pragma unroll
                for (int j = 0; j < 8; j++)
                    acc[i][j] = fmaf(a[i], b[j], acc[i][j]);
        }
        __syncthreads();
    }

    // Epilogue: add bias, store float4.
#pragma unroll
    for (int i = 0; i < 8; i++) {
        int r = rowBase + ty * 8 + i;
#pragma unroll
        for (int j4 = 0; j4 < 2; j4++) {
            int c = colBase + tx * 8 + j4 * 4;
            float4 bb = *reinterpret_cast<const float4*>(bias + c);
            float4 o;
            o.x = acc[i][j4 * 4 + 0] + bb.x;
            o.y = acc[i][j4 * 4 + 1] + bb.y;
            o.z = acc[i][j4 * 4 + 2] + bb.z;
            o.w = acc[i][j4 * 4 + 3] + bb.w;
            *reinterpret_cast<float4*>(C + r * Ncols + c) = o;
        }
    }
}

// QKV projections fused into one launch: blockIdx.z selects the weight set.
__global__ __launch_bounds__(256, 2)
void gemm_qkv_kernel(const float* __restrict__ y,
                     const float* __restrict__ Wq, const float* __restrict__ bq,
                     const float* __restrict__ Wk, const float* __restrict__ bk,
                     const float* __restrict__ Wv, const float* __restrict__ bv)
{
    const float* W; const float* bias; float* C;
    if (blockIdx.z == 0)      { W = Wq; bias = bq; C = g_Q; }
    else if (blockIdx.z == 1) { W = Wk; bias = bk; C = g_K; }
    else                      { W = Wv; bias = bv; C = g_V; }
    gemm_body(y, W, bias, C);
}

__global__ __launch_bounds__(256, 2)
void gemm_out_kernel(const float* __restrict__ Wo,
                     const float* __restrict__ bo,
                     float* __restrict__ out)
{
    gemm_body(g_O, Wo, bo, out);
}

// ---------------------------------------------------------------------------
// Flash attention: one block per (q-tile of 64, head, batch).
// 256 threads; per-thread 4x4 register tiles for both S=QK^T and O+=P*V.
// Online softmax with running (max, sum) per query row.
// Dynamic smem: Qs[64][64](d-major) Ks[64][64](d-major) Vs[64][64](j-major)
//               Ps[64][64](q-major) = 64 KB.
// ---------------------------------------------------------------------------
__global__ __launch_bounds__(256, 2)
void attn_flash_kernel()
{
    extern __shared__ float sm[];
    float* Qs = sm;              // Qs[d*64 + q]
    float* Ks = sm + 64 * 64;    // Ks[d*64 + k]
    float* Vs = sm + 2 * 64 * 64;  // Vs[j*64 + d]
    float* Ps = sm + 3 * 64 * 64;  // Ps[q*64 + j]

    const int tid = threadIdx.x;
    const int tx = tid & 15;   // key-col group in S phase, d-col group in AV
    const int ty = tid >> 4;   // query-row group
    const int q0 = blockIdx.x * QTILE;
    const int h  = blockIdx.y;
    const int b  = blockIdx.z;

    const int rowStride = Hh * Dh;  // 1024 floats between consecutive n
    const float* Qg = g_Q + (b * Nn) * rowStride + h * Dh;
    const float* Kg = g_K + (b * Nn) * rowStride + h * Dh;
    const float* Vg = g_V + (b * Nn) * rowStride + h * Dh;

    // Load Q tile transposed: Qs[d][q].  1024 float4, 4 per thread.
#pragma unroll
    for (int i = 0; i < 4; i++) {
        int f = tid + i * 256;
        int q = f >> 4;             // 0..63
        int dc = (f & 15) << 2;     // 0,4,..,60
        float4 v = *reinterpret_cast<const float4*>(Qg + (q0 + q) * rowStride + dc);
        Qs[(dc + 0) * 64 + q] = v.x;
        Qs[(dc + 1) * 64 + q] = v.y;
        Qs[(dc + 2) * 64 + q] = v.z;
        Qs[(dc + 3) * 64 + q] = v.w;
    }

    float m_run[4], l_run[4], o_acc[4][4];
#pragma unroll
    for (int i = 0; i < 4; i++) {
        m_run[i] = -1e30f;
        l_run[i] = 0.0f;
#pragma unroll
        for (int j = 0; j < 4; j++) o_acc[i][j] = 0.0f;
    }

    const float SCALE = 0.125f;  // 1/sqrt(64)

    for (int kt = 0; kt < Nn / KTILE; kt++) {
        __syncthreads();  // prior AV done with Ks/Vs/Ps (and Qs visible, kt=0)
        const int k0 = kt * KTILE;
        // Load K (transposed -> Ks[d][k]) and V (natural -> Vs[j][d]).
#pragma unroll
        for (int i = 0; i < 4; i++) {
            int f = tid + i * 256;
            int r = f >> 4;
            int dc = (f & 15) << 2;
            float4 kv = *reinterpret_cast<const float4*>(Kg + (k0 + r) * rowStride + dc);
            Ks[(dc + 0) * 64 + r] = kv.x;
            Ks[(dc + 1) * 64 + r] = kv.y;
            Ks[(dc + 2) * 64 + r] = kv.z;
            Ks[(dc + 3) * 64 + r] = kv.w;
            float4 vv = *reinterpret_cast<const float4*>(Vg + (k0 + r) * rowStride + dc);
            *reinterpret_cast<float4*>(Vs + r * 64 + dc) = vv;
        }
        __syncthreads();

        // S[i][j] = sum_d Q[q][d] * K[k][d], q = ty*4+i, k = tx*4+j
        float s[4][4];
#pragma unroll
        for (int i = 0; i < 4; i++)
#pragma unroll
            for (int j = 0; j < 4; j++) s[i][j] = 0.0f;

#pragma unroll
        for (int d = 0; d < 64; d++) {
            float qa[4], kb[4];
            *reinterpret_cast<float4*>(qa) =
                *reinterpret_cast<const float4*>(Qs + d * 64 + ty * 4);
            *reinterpret_cast<float4*>(kb) =
                *reinterpret_cast<const float4*>(Ks + d * 64 + tx * 4);
#pragma unroll
            for (int i = 0; i < 4; i++)
#pragma unroll
                for (int j = 0; j < 4; j++)
                    s[i][j] = fmaf(qa[i], kb[j], s[i][j]);
        }

        // Online softmax update per query row.
#pragma unroll
        for (int i = 0; i < 4; i++) {
#pragma unroll
            for (int j = 0; j < 4; j++) s[i][j] *= SCALE;
            float tm = fmaxf(fmaxf(s[i][0], s[i][1]), fmaxf(s[i][2], s[i][3]));
            // Row groups occupy 16 consecutive lanes: xor 1..8 stays in-group.
#pragma unroll
            for (int off = 1; off < 16; off <<= 1)
                tm = fmaxf(tm, __shfl_xor_sync(0xffffffffu, tm, off));
            float nm = fmaxf(m_run[i], tm);
            float corr = __expf(m_run[i] - nm);
            float ps = 0.0f;
#pragma unroll
            for (int j = 0; j < 4; j++) {
                s[i][j] = __expf(s[i][j] - nm);
                ps += s[i][j];
            }
#pragma unroll
            for (int off = 1; off < 16; off <<= 1)
                ps += __shfl_xor_sync(0xffffffffu, ps, off);
            l_run[i] = l_run[i] * corr + ps;
            m_run[i] = nm;
#pragma unroll
            for (int j = 0; j < 4; j++) o_acc[i][j] *= corr;
        }

        // Store P tile q-major (vectorized, conflict-light).
#pragma unroll
        for (int i = 0; i < 4; i++) {
            float4 p4 = make_float4(s[i][0], s[i][1], s[i][2], s[i][3]);
            *reinterpret_cast<float4*>(Ps + (ty * 4 + i) * 64 + tx * 4) = p4;
        }
        __syncthreads();

        // O[q][d] += sum_j P[q][j] * V[j][d], d = tx*4+..
#pragma unroll
        for (int j0 = 0; j0 < 64; j0 += 4) {
            float p[4][4], v[4][4];
#pragma unroll
            for (int i = 0; i < 4; i++)
                *reinterpret_cast<float4*>(p[i]) =
                    *reinterpret_cast<const float4*>(Ps + (ty * 4 + i) * 64 + j0);
#pragma unroll
            for (int jj = 0; jj < 4; jj++)
                *reinterpret_cast<float4*>(v[jj]) =
                    *reinterpret_cast<const float4*>(Vs + (j0 + jj) * 64 + tx * 4);
#pragma unroll
            for (int i = 0; i < 4; i++)
#pragma unroll
                for (int d = 0; d < 4; d++)
#pragma unroll
                    for (int jj = 0; jj < 4; jj++)
                        o_acc[i][d] = fmaf(p[i][jj], v[jj][d], o_acc[i][d]);
        }
    }

    // Normalize and write O in (b, n, h, d) layout.
    float* Og = g_O + (b * Nn) * rowStride + h * Dh;
#pragma unroll
    for (int i = 0; i < 4; i++) {
        float inv = 1.0f / l_run[i];
        float4 o = make_float4(o_acc[i][0] * inv, o_acc[i][1] * inv,
                               o_acc[i][2] * inv, o_acc[i][3] * inv);
        *reinterpret_cast<float4*>(Og + (q0 + ty * 4 + i) * rowStride + tx * 4) = o;
    }
}

// ---------------------------------------------------------------------------
// Launch
// ---------------------------------------------------------------------------
extern "C" void kernel_launch(void* const* d_in, const int* in_sizes, int n_in,
                              void* d_out, int out_size)
{
    const float* y  = (const float*)d_in[0];
    const float* Wq = (const float*)d_in[1];
    const float* bq = (const float*)d_in[2];
    const float* Wk = (const float*)d_in[3];
    const float* bk = (const float*)d_in[4];
    const float* Wv = (const float*)d_in[5];
    const float* bv = (const float*)d_in[6];
    const float* Wo = (const float*)d_in[7];
    const float* bo = (const float*)d_in[8];
    float* out = (float*)d_out;

    // 64 KB dynamic smem for the flash kernel (idempotent; not an allocation).
    cudaFuncSetAttribute(attn_flash_kernel,
                         cudaFuncAttributeMaxDynamicSharedMemorySize, 65536);

    // 1) Q/K/V projections: 3 fused GEMMs [4096,1024]x[1024,1024]^T.
    dim3 gq(DM / 128, Mrows / 128, 3);   // (8, 32, 3)
    gemm_qkv_kernel<<<gq, 256>>>(y, Wq, bq, Wk, bk, Wv, bv);

    // 2) Flash attention per (q-tile, head, batch).
    dim3 ga(Nn / QTILE, Hh, Bb);         // (32, 16, 2)
    attn_flash_kernel<<<ga, 256, 65536>>>();

    // 3) Output projection [4096,1024]x[1024,1024]^T -> d_out.
    dim3 go(DM / 128, Mrows / 128);      // (8, 32)
    gemm_out_kernel<<<go, 256>>>(Wo, bo, out);
}

// round 6
// speedup vs baseline: 1.3852x; 1.3852x over previous
#include <cuda_runtime.h>
#include <cuda_bf16.h>
#include <cstdint>

// ---------------------------------------------------------------------------
// Multi-head attention: y -> Q,K,V proj -> softmax(QK^T/sqrt(d))V -> out proj
// B=2, N=2048, D_MODEL=1024, H=16, D_K=D_V=64.
// Round 6: projections via warp-level mma.sync bf16 (split-fp32, 3 MMAs) —
//          tcgen05 is unusable here (harness PTX target is compute_103, which
//          rejects all 'a'-suffix features). Attention still fp32 SIMT.
// ---------------------------------------------------------------------------

namespace {
constexpr int Bb = 2;
constexpr int Nn = 2048;
constexpr int DM = 1024;   // d_model
constexpr int Hh = 16;
constexpr int Dh = 64;     // head dim
constexpr int Mrows = Bb * Nn;          // 4096 token rows
constexpr int QTILE = 64;
constexpr int KTILE = 64;

constexpr int KC = 32;     // k elems per GEMM chunk
constexpr int NCHUNK = DM / KC;   // 32
constexpr int PAD = 40;    // smem row stride in bf16 elems (80B: conflict-free LDSM)
}

// Scratch: Q,K,V,O in (b, n, h, d) layout = [Mrows][DM] row-major fp32.
__device__ float g_Q[Mrows * DM];
__device__ float g_K[Mrows * DM];
__device__ float g_V[Mrows * DM];
__device__ float g_O[Mrows * DM];

// ---------------------------------------------------------------------------
// helpers
// ---------------------------------------------------------------------------
__device__ __forceinline__ uint32_t smem_u32(const void* p) {
    uint32_t a;
    asm("{ .reg .u64 t; cvta.to.shared.u64 t, %1; cvt.u32.u64 %0, t; }"
        : "=r"(a) : "l"(p));
    return a;
}

// pack two floats -> bf16x2 (bits[31:16]=bf16(hiArg), bits[15:0]=bf16(loArg))
__device__ __forceinline__ uint32_t pack_bf16x2(float hiArg, float loArg) {
    uint32_t r;
    asm("cvt.rn.bf16x2.f32 %0, %1, %2;" : "=r"(r) : "f"(hiArg), "f"(loArg));
    return r;
}
__device__ __forceinline__ float bf_lo(uint32_t p) { return __uint_as_float(p << 16); }
__device__ __forceinline__ float bf_hi(uint32_t p) { return __uint_as_float(p & 0xFFFF0000u); }

__device__ __forceinline__ void ldsm_x4(uint32_t* r, uint32_t addr) {
    asm volatile("ldmatrix.sync.aligned.m8n8.x4.shared.b16 {%0,%1,%2,%3}, [%4];"
                 : "=r"(r[0]), "=r"(r[1]), "=r"(r[2]), "=r"(r[3]) : "r"(addr));
}
__device__ __forceinline__ void ldsm_x2(uint32_t* r, uint32_t addr) {
    asm volatile("ldmatrix.sync.aligned.m8n8.x2.shared.b16 {%0,%1}, [%2];"
                 : "=r"(r[0]), "=r"(r[1]) : "r"(addr));
}
__device__ __forceinline__ void mma16816(float* c, const uint32_t* a,
                                         const uint32_t* b) {
    asm volatile(
        "mma.sync.aligned.m16n8k16.row.col.f32.bf16.bf16.f32 "
        "{%0,%1,%2,%3}, {%4,%5,%6,%7}, {%8,%9}, {%0,%1,%2,%3};"
        : "+f"(c[0]), "+f"(c[1]), "+f"(c[2]), "+f"(c[3])
        : "r"(a[0]), "r"(a[1]), "r"(a[2]), "r"(a[3]), "r"(b[0]), "r"(b[1]));
}

// ---------------------------------------------------------------------------
// GEMM: C[m][n] = sum_k A[m][k]*W[n][k] + bias[n]   (both operands k-major)
// Block 128x128, 8 warps in 2(M)x4(N), warp tile 64x32, K-chunk 32.
// Split-fp32: per chunk issue (Ah,Bh), (Ah,Bl), (Al,Bh).
// ---------------------------------------------------------------------------
__device__ __forceinline__ void gemm_mma_body(
    const float* __restrict__ A, const float* __restrict__ W,
    const float* __restrict__ bias, float* __restrict__ C)
{
    __shared__ __align__(16) uint16_t sAh[128 * PAD];
    __shared__ __align__(16) uint16_t sAl[128 * PAD];
    __shared__ __align__(16) uint16_t sBh[128 * PAD];
    __shared__ __align__(16) uint16_t sBl[128 * PAD];

    const int tid = threadIdx.x;
    const int lane = tid & 31;
    const int wid = tid >> 5;
    const int warpM = wid & 1;        // 0..1  -> 64 rows each
    const int warpN = wid >> 1;       // 0..3  -> 32 cols each
    const int rowBase = blockIdx.y * 128;
    const int colBase = blockIdx.x * 128;

    float acc[4][4][4];
#pragma unroll
    for (int mt = 0; mt < 4; mt++)
#pragma unroll
        for (int nt = 0; nt < 4; nt++)
#pragma unroll
            for (int r = 0; r < 4; r++) acc[mt][nt][r] = 0.0f;

    const uint32_t aBaseH = smem_u32(sAh);
    const uint32_t aBaseL = smem_u32(sAl);
    const uint32_t bBaseH = smem_u32(sBh);
    const uint32_t bBaseL = smem_u32(sBl);

    // ldmatrix lane->address offsets
    const int aRowOff = warpM * 64 + (lane & 15);
    const int aColOff = (lane >> 4) * 8;
    const int bRowOff = warpN * 32 + (lane & 7);
    const int bColOff = ((lane >> 3) & 1) * 8;

    for (int kc = 0; kc < NCHUNK; kc++) {
        const int k0 = kc * KC;
        __syncthreads();   // previous chunk's fragments fully consumed

        // Convert fp32 -> (hi, lo) bf16 tiles. 1024 float4 per operand,
        // 4 per thread each.
#pragma unroll
        for (int i = 0; i < 4; i++) {
            const int f = tid + i * 256;
            const int r = f >> 3;          // row 0..127
            const int c4 = f & 7;          // float4 idx within 32-elem chunk

            float4 va = *reinterpret_cast<const float4*>(
                A + (size_t)(rowBase + r) * DM + k0 + c4 * 4);
            uint32_t ah0 = pack_bf16x2(va.y, va.x);
            uint32_t ah1 = pack_bf16x2(va.w, va.z);
            uint32_t al0 = pack_bf16x2(va.y - bf_hi(ah0), va.x - bf_lo(ah0));
            uint32_t al1 = pack_bf16x2(va.w - bf_hi(ah1), va.z - bf_lo(ah1));
            *reinterpret_cast<uint2*>(&sAh[r * PAD + c4 * 4]) = make_uint2(ah0, ah1);
            *reinterpret_cast<uint2*>(&sAl[r * PAD + c4 * 4]) = make_uint2(al0, al1);

            float4 vb = *reinterpret_cast<const float4*>(
                W + (size_t)(colBase + r) * DM + k0 + c4 * 4);
            uint32_t bh0 = pack_bf16x2(vb.y, vb.x);
            uint32_t bh1 = pack_bf16x2(vb.w, vb.z);
            uint32_t bl0 = pack_bf16x2(vb.y - bf_hi(bh0), vb.x - bf_lo(bh0));
            uint32_t bl1 = pack_bf16x2(vb.w - bf_hi(bh1), vb.z - bf_lo(bh1));
            *reinterpret_cast<uint2*>(&sBh[r * PAD + c4 * 4]) = make_uint2(bh0, bh1);
            *reinterpret_cast<uint2*>(&sBl[r * PAD + c4 * 4]) = make_uint2(bl0, bl1);
        }
        __syncthreads();

        // 3 split passes x 2 k16 steps
#pragma unroll
        for (int s = 0; s < 3; s++) {
            const uint32_t aB = (s == 2) ? aBaseL : aBaseH;
            const uint32_t bB = (s == 1) ? bBaseL : bBaseH;
#pragma unroll
            for (int kk = 0; kk < 2; kk++) {
                const int k16 = kk * 16;
                uint32_t bf[4][2];
#pragma unroll
                for (int nt = 0; nt < 4; nt++)
                    ldsm_x2(bf[nt],
                            bB + (uint32_t)(((bRowOff + nt * 8) * PAD + k16 + bColOff) * 2));
#pragma unroll
                for (int mt = 0; mt < 4; mt++) {
                    uint32_t af[4];
                    ldsm_x4(af,
                            aB + (uint32_t)(((aRowOff + mt * 16) * PAD + k16 + aColOff) * 2));
#pragma unroll
                    for (int nt = 0; nt < 4; nt++)
                        mma16816(acc[mt][nt], af, bf[nt]);
                }
            }
        }
    }

    // Epilogue: mma C-fragment layout -> global, with bias.
    const int g = lane >> 2;
    const int t4 = lane & 3;
#pragma unroll
    for (int mt = 0; mt < 4; mt++) {
#pragma unroll
        for (int nt = 0; nt < 4; nt++) {
            const int row0 = rowBase + warpM * 64 + mt * 16 + g;
            const int col = colBase + warpN * 32 + nt * 8 + t4 * 2;
            float2 bb = *reinterpret_cast<const float2*>(bias + col);
            float2 o0 = make_float2(acc[mt][nt][0] + bb.x, acc[mt][nt][1] + bb.y);
            float2 o1 = make_float2(acc[mt][nt][2] + bb.x, acc[mt][nt][3] + bb.y);
            *reinterpret_cast<float2*>(C + (size_t)row0 * DM + col) = o0;
            *reinterpret_cast<float2*>(C + (size_t)(row0 + 8) * DM + col) = o1;
        }
    }
}

__global__ __launch_bounds__(256, 2)
void gemm_qkv_kernel(const float* __restrict__ y,
                     const float* __restrict__ Wq, const float* __restrict__ bq,
                     const float* __restrict__ Wk, const float* __restrict__ bk,
                     const float* __restrict__ Wv, const float* __restrict__ bv)
{
    const float* W; const float* bias; float* C;
    if (blockIdx.z == 0)      { W = Wq; bias = bq; C = g_Q; }
    else if (blockIdx.z == 1) { W = Wk; bias = bk; C = g_K; }
    else                      { W = Wv; bias = bv; C = g_V; }
    gemm_mma_body(y, W, bias, C);
}

__global__ __launch_bounds__(256, 2)
void gemm_out_kernel(const float* __restrict__ Wo,
                     const float* __restrict__ bo,
                     float* __restrict__ out)
{
    gemm_mma_body(g_O, Wo, bo, out);
}

// ---------------------------------------------------------------------------
// Flash attention (fp32 SIMT, unchanged from round 4 — proven correct).
// ---------------------------------------------------------------------------
__global__ __launch_bounds__(256, 2)
void attn_flash_kernel()
{
    extern __shared__ __align__(1024) char smc[];
    float* sm = reinterpret_cast<float*>(smc);
    float* Qs = sm;                // Qs[d*64 + q]
    float* Ks = sm + 64 * 64;      // Ks[d*64 + k]
    float* Vs = sm + 2 * 64 * 64;  // Vs[j*64 + d]
    float* Ps = sm + 3 * 64 * 64;  // Ps[q*64 + j]

    const int tid = threadIdx.x;
    const int tx = tid & 15;
    const int ty = tid >> 4;
    const int q0 = blockIdx.x * QTILE;
    const int h  = blockIdx.y;
    const int b  = blockIdx.z;

    const int rowStride = Hh * Dh;  // 1024
    const float* Qg = g_Q + (size_t)(b * Nn) * rowStride + h * Dh;
    const float* Kg = g_K + (size_t)(b * Nn) * rowStride + h * Dh;
    const float* Vg = g_V + (size_t)(b * Nn) * rowStride + h * Dh;

#pragma unroll
    for (int i = 0; i < 4; i++) {
        int f = tid + i * 256;
        int q = f >> 4;
        int dc = (f & 15) << 2;
        float4 v = *reinterpret_cast<const float4*>(Qg + (size_t)(q0 + q) * rowStride + dc);
        Qs[(dc + 0) * 64 + q] = v.x;
        Qs[(dc + 1) * 64 + q] = v.y;
        Qs[(dc + 2) * 64 + q] = v.z;
        Qs[(dc + 3) * 64 + q] = v.w;
    }

    float m_run[4], l_run[4], o_acc[4][4];
#pragma unroll
    for (int i = 0; i < 4; i++) {
        m_run[i] = -1e30f;
        l_run[i] = 0.0f;
#pragma unroll
        for (int j = 0; j < 4; j++) o_acc[i][j] = 0.0f;
    }

    const float SCALE = 0.125f;

    for (int kt = 0; kt < Nn / KTILE; kt++) {
        __syncthreads();
        const int k0 = kt * KTILE;
#pragma unroll
        for (int i = 0; i < 4; i++) {
            int f = tid + i * 256;
            int r = f >> 4;
            int dc = (f & 15) << 2;
            float4 kv = *reinterpret_cast<const float4*>(Kg + (size_t)(k0 + r) * rowStride + dc);
            Ks[(dc + 0) * 64 + r] = kv.x;
            Ks[(dc + 1) * 64 + r] = kv.y;
            Ks[(dc + 2) * 64 + r] = kv.z;
            Ks[(dc + 3) * 64 + r] = kv.w;
            float4 vv = *reinterpret_cast<const float4*>(Vg + (size_t)(k0 + r) * rowStride + dc);
            *reinterpret_cast<float4*>(Vs + r * 64 + dc) = vv;
        }
        __syncthreads();

        float s[4][4];
#pragma unroll
        for (int i = 0; i < 4; i++)
#pragma unroll
            for (int j = 0; j < 4; j++) s[i][j] = 0.0f;

#pragma unroll
        for (int d = 0; d < 64; d++) {
            float qa[4], kb[4];
            *reinterpret_cast<float4*>(qa) =
                *reinterpret_cast<const float4*>(Qs + d * 64 + ty * 4);
            *reinterpret_cast<float4*>(kb) =
                *reinterpret_cast<const float4*>(Ks + d * 64 + tx * 4);
#pragma unroll
            for (int i = 0; i < 4; i++)
#pragma unroll
                for (int j = 0; j < 4; j++)
                    s[i][j] = fmaf(qa[i], kb[j], s[i][j]);
        }

#pragma unroll
        for (int i = 0; i < 4; i++) {
#pragma unroll
            for (int j = 0; j < 4; j++) s[i][j] *= SCALE;
            float tm = fmaxf(fmaxf(s[i][0], s[i][1]), fmaxf(s[i][2], s[i][3]));
#pragma unroll
            for (int off = 1; off < 16; off <<= 1)
                tm = fmaxf(tm, __shfl_xor_sync(0xffffffffu, tm, off));
            float nm = fmaxf(m_run[i], tm);
            float corr = __expf(m_run[i] - nm);
            float ps = 0.0f;
#pragma unroll
            for (int j = 0; j < 4; j++) {
                s[i][j] = __expf(s[i][j] - nm);
                ps += s[i][j];
            }
#pragma unroll
            for (int off = 1; off < 16; off <<= 1)
                ps += __shfl_xor_sync(0xffffffffu, ps, off);
            l_run[i] = l_run[i] * corr + ps;
            m_run[i] = nm;
#pragma unroll
            for (int j = 0; j < 4; j++) o_acc[i][j] *= corr;
        }

#pragma unroll
        for (int i = 0; i < 4; i++) {
            float4 p4 = make_float4(s[i][0], s[i][1], s[i][2], s[i][3]);
            *reinterpret_cast<float4*>(Ps + (ty * 4 + i) * 64 + tx * 4) = p4;
        }
        __syncthreads();

#pragma unroll
        for (int j0 = 0; j0 < 64; j0 += 4) {
            float p[4][4], v[4][4];
#pragma unroll
            for (int i = 0; i < 4; i++)
                *reinterpret_cast<float4*>(p[i]) =
                    *reinterpret_cast<const float4*>(Ps + (ty * 4 + i) * 64 + j0);
#pragma unroll
            for (int jj = 0; jj < 4; jj++)
                *reinterpret_cast<float4*>(v[jj]) =
                    *reinterpret_cast<const float4*>(Vs + (j0 + jj) * 64 + tx * 4);
#pragma unroll
            for (int i = 0; i < 4; i++)
#pragma unroll
                for (int d = 0; d < 4; d++)
#pragma unroll
                    for (int jj = 0; jj < 4; jj++)
                        o_acc[i][d] = fmaf(p[i][jj], v[jj][d], o_acc[i][d]);
        }
    }

    float* Og = g_O + (size_t)(b * Nn) * rowStride + h * Dh;
#pragma unroll
    for (int i = 0; i < 4; i++) {
        float inv = 1.0f / l_run[i];
        float4 o = make_float4(o_acc[i][0] * inv, o_acc[i][1] * inv,
                               o_acc[i][2] * inv, o_acc[i][3] * inv);
        *reinterpret_cast<float4*>(Og + (size_t)(q0 + ty * 4 + i) * rowStride + tx * 4) = o;
    }
}

// ---------------------------------------------------------------------------
// Launch
// ---------------------------------------------------------------------------
extern "C" void kernel_launch(void* const* d_in, const int* in_sizes, int n_in,
                              void* d_out, int out_size)
{
    const float* y  = (const float*)d_in[0];
    const float* Wq = (const float*)d_in[1];
    const float* bq = (const float*)d_in[2];
    const float* Wk = (const float*)d_in[3];
    const float* bk = (const float*)d_in[4];
    const float* Wv = (const float*)d_in[5];
    const float* bv = (const float*)d_in[6];
    const float* Wo = (const float*)d_in[7];
    const float* bo = (const float*)d_in[8];
    float* out = (float*)d_out;

    cudaFuncSetAttribute(attn_flash_kernel,
                         cudaFuncAttributeMaxDynamicSharedMemorySize, 65536);

    // 1) Q/K/V projections (mma.sync split-bf16).
    dim3 gq(DM / 128, Mrows / 128, 3);   // (8, 32, 3)
    gemm_qkv_kernel<<<gq, 256>>>(y, Wq, bq, Wk, bk, Wv, bv);

    // 2) Flash attention per (q-tile, head, batch).
    dim3 ga(Nn / QTILE, Hh, Bb);         // (32, 16, 2)
    attn_flash_kernel<<<ga, 256, 65536>>>();

    // 3) Output projection (mma.sync split-bf16) -> d_out.
    dim3 go(DM / 128, Mrows / 128);      // (8, 32)
    gemm_out_kernel<<<go, 256>>>(Wo, bo, out);
}

// round 9
// speedup vs baseline: 2.9570x; 2.1347x over previous
#include <cuda_runtime.h>
#include <cuda_bf16.h>
#include <cstdint>

// ---------------------------------------------------------------------------
// Multi-head attention: y -> Q,K,V proj -> softmax(QK^T/sqrt(d))V -> out proj
// B=2, N=2048, D_MODEL=1024, H=16, D_K=D_V=64.
// Round 7: everything on mma.sync bf16 with split-fp32 (3-MMA) precision.
//   - projections: unchanged from round 6 (validated, 255us qkv)
//   - attention: new FA2-style mma.sync kernel (was fp32 SIMT, 1065us)
// ---------------------------------------------------------------------------

namespace {
constexpr int Bb = 2;
constexpr int Nn = 2048;
constexpr int DM = 1024;   // d_model
constexpr int Hh = 16;
constexpr int Dh = 64;     // head dim
constexpr int Mrows = Bb * Nn;          // 4096 token rows

constexpr int KC = 32;     // k elems per GEMM chunk
constexpr int NCHUNK = DM / KC;   // 32
constexpr int PAD = 40;    // gemm smem row stride (bf16 elems)

constexpr int AST = 72;    // attention smem row stride (64 + 8 bf16)
// dyn smem: Qh/Ql 128 rows + Kh/Kl/Vh/Vl 64 rows each = 512 rows * 72 * 2B
constexpr int ATTN_SMEM = (128 * 2 + 64 * 4) * AST * 2;   // 73728
}

// Scratch: Q,K,V,O in (b, n, h, d) layout = [Mrows][DM] row-major fp32.
__device__ float g_Q[Mrows * DM];
__device__ float g_K[Mrows * DM];
__device__ float g_V[Mrows * DM];
__device__ float g_O[Mrows * DM];

// ---------------------------------------------------------------------------
// helpers
// ---------------------------------------------------------------------------
__device__ __forceinline__ uint32_t smem_u32(const void* p) {
    uint32_t a;
    asm("{ .reg .u64 t; cvta.to.shared.u64 t, %1; cvt.u32.u64 %0, t; }"
        : "=r"(a) : "l"(p));
    return a;
}

// pack two floats -> bf16x2 (bits[31:16]=bf16(hiArg), bits[15:0]=bf16(loArg))
__device__ __forceinline__ uint32_t pack_bf16x2(float hiArg, float loArg) {
    uint32_t r;
    asm("cvt.rn.bf16x2.f32 %0, %1, %2;" : "=r"(r) : "f"(hiArg), "f"(loArg));
    return r;
}
__device__ __forceinline__ float bf_lo(uint32_t p) { return __uint_as_float(p << 16); }
__device__ __forceinline__ float bf_hi(uint32_t p) { return __uint_as_float(p & 0xFFFF0000u); }

__device__ __forceinline__ void ldsm_x4(uint32_t* r, uint32_t addr) {
    asm volatile("ldmatrix.sync.aligned.m8n8.x4.shared.b16 {%0,%1,%2,%3}, [%4];"
                 : "=r"(r[0]), "=r"(r[1]), "=r"(r[2]), "=r"(r[3]) : "r"(addr));
}
__device__ __forceinline__ void ldsm_x4_t(uint32_t* r, uint32_t addr) {
    asm volatile("ldmatrix.sync.aligned.m8n8.x4.trans.shared.b16 {%0,%1,%2,%3}, [%4];"
                 : "=r"(r[0]), "=r"(r[1]), "=r"(r[2]), "=r"(r[3]) : "r"(addr));
}
__device__ __forceinline__ void ldsm_x2(uint32_t* r, uint32_t addr) {
    asm volatile("ldmatrix.sync.aligned.m8n8.x2.shared.b16 {%0,%1}, [%2];"
                 : "=r"(r[0]), "=r"(r[1]) : "r"(addr));
}
__device__ __forceinline__ void mma16816(float* c, const uint32_t* a,
                                         const uint32_t* b) {
    asm volatile(
        "mma.sync.aligned.m16n8k16.row.col.f32.bf16.bf16.f32 "
        "{%0,%1,%2,%3}, {%4,%5,%6,%7}, {%8,%9}, {%0,%1,%2,%3};"
        : "+f"(c[0]), "+f"(c[1]), "+f"(c[2]), "+f"(c[3])
        : "r"(a[0]), "r"(a[1]), "r"(a[2]), "r"(a[3]), "r"(b[0]), "r"(b[1]));
}

// ---------------------------------------------------------------------------
// Projection GEMM (unchanged from round 6): C[m][n] = sum_k A[m][k]*W[n][k]+b
// ---------------------------------------------------------------------------
__device__ __forceinline__ void gemm_mma_body(
    const float* __restrict__ A, const float* __restrict__ W,
    const float* __restrict__ bias, float* __restrict__ C)
{
    __shared__ __align__(16) uint16_t sAh[128 * PAD];
    __shared__ __align__(16) uint16_t sAl[128 * PAD];
    __shared__ __align__(16) uint16_t sBh[128 * PAD];
    __shared__ __align__(16) uint16_t sBl[128 * PAD];

    const int tid = threadIdx.x;
    const int lane = tid & 31;
    const int wid = tid >> 5;
    const int warpM = wid & 1;
    const int warpN = wid >> 1;
    const int rowBase = blockIdx.y * 128;
    const int colBase = blockIdx.x * 128;

    float acc[4][4][4];
#pragma unroll
    for (int mt = 0; mt < 4; mt++)
#pragma unroll
        for (int nt = 0; nt < 4; nt++)
#pragma unroll
            for (int r = 0; r < 4; r++) acc[mt][nt][r] = 0.0f;

    const uint32_t aBaseH = smem_u32(sAh);
    const uint32_t aBaseL = smem_u32(sAl);
    const uint32_t bBaseH = smem_u32(sBh);
    const uint32_t bBaseL = smem_u32(sBl);

    const int aRowOff = warpM * 64 + (lane & 15);
    const int aColOff = (lane >> 4) * 8;
    const int bRowOff = warpN * 32 + (lane & 7);
    const int bColOff = ((lane >> 3) & 1) * 8;

    for (int kc = 0; kc < NCHUNK; kc++) {
        const int k0 = kc * KC;
        __syncthreads();

#pragma unroll
        for (int i = 0; i < 4; i++) {
            const int f = tid + i * 256;
            const int r = f >> 3;
            const int c4 = f & 7;

            float4 va = *reinterpret_cast<const float4*>(
                A + (size_t)(rowBase + r) * DM + k0 + c4 * 4);
            uint32_t ah0 = pack_bf16x2(va.y, va.x);
            uint32_t ah1 = pack_bf16x2(va.w, va.z);
            uint32_t al0 = pack_bf16x2(va.y - bf_hi(ah0), va.x - bf_lo(ah0));
            uint32_t al1 = pack_bf16x2(va.w - bf_hi(ah1), va.z - bf_lo(ah1));
            *reinterpret_cast<uint2*>(&sAh[r * PAD + c4 * 4]) = make_uint2(ah0, ah1);
            *reinterpret_cast<uint2*>(&sAl[r * PAD + c4 * 4]) = make_uint2(al0, al1);

            float4 vb = *reinterpret_cast<const float4*>(
                W + (size_t)(colBase + r) * DM + k0 + c4 * 4);
            uint32_t bh0 = pack_bf16x2(vb.y, vb.x);
            uint32_t bh1 = pack_bf16x2(vb.w, vb.z);
            uint32_t bl0 = pack_bf16x2(vb.y - bf_hi(bh0), vb.x - bf_lo(bh0));
            uint32_t bl1 = pack_bf16x2(vb.w - bf_hi(bh1), vb.z - bf_lo(bh1));
            *reinterpret_cast<uint2*>(&sBh[r * PAD + c4 * 4]) = make_uint2(bh0, bh1);
            *reinterpret_cast<uint2*>(&sBl[r * PAD + c4 * 4]) = make_uint2(bl0, bl1);
        }
        __syncthreads();

#pragma unroll
        for (int s = 0; s < 3; s++) {
            const uint32_t aB = (s == 2) ? aBaseL : aBaseH;
            const uint32_t bB = (s == 1) ? bBaseL : bBaseH;
#pragma unroll
            for (int kk = 0; kk < 2; kk++) {
                const int k16 = kk * 16;
                uint32_t bf[4][2];
#pragma unroll
                for (int nt = 0; nt < 4; nt++)
                    ldsm_x2(bf[nt],
                            bB + (uint32_t)(((bRowOff + nt * 8) * PAD + k16 + bColOff) * 2));
#pragma unroll
                for (int mt = 0; mt < 4; mt++) {
                    uint32_t af[4];
                    ldsm_x4(af,
                            aB + (uint32_t)(((aRowOff + mt * 16) * PAD + k16 + aColOff) * 2));
#pragma unroll
                    for (int nt = 0; nt < 4; nt++)
                        mma16816(acc[mt][nt], af, bf[nt]);
                }
            }
        }
    }

    const int g = lane >> 2;
    const int t4 = lane & 3;
#pragma unroll
    for (int mt = 0; mt < 4; mt++) {
#pragma unroll
        for (int nt = 0; nt < 4; nt++) {
            const int row0 = rowBase + warpM * 64 + mt * 16 + g;
            const int col = colBase + warpN * 32 + nt * 8 + t4 * 2;
            float2 bb = *reinterpret_cast<const float2*>(bias + col);
            float2 o0 = make_float2(acc[mt][nt][0] + bb.x, acc[mt][nt][1] + bb.y);
            float2 o1 = make_float2(acc[mt][nt][2] + bb.x, acc[mt][nt][3] + bb.y);
            *reinterpret_cast<float2*>(C + (size_t)row0 * DM + col) = o0;
            *reinterpret_cast<float2*>(C + (size_t)(row0 + 8) * DM + col) = o1;
        }
    }
}

__global__ __launch_bounds__(256, 2)
void gemm_qkv_kernel(const float* __restrict__ y,
                     const float* __restrict__ Wq, const float* __restrict__ bq,
                     const float* __restrict__ Wk, const float* __restrict__ bk,
                     const float* __restrict__ Wv, const float* __restrict__ bv)
{
    const float* W; const float* bias; float* C;
    if (blockIdx.z == 0)      { W = Wq; bias = bq; C = g_Q; }
    else if (blockIdx.z == 1) { W = Wk; bias = bk; C = g_K; }
    else                      { W = Wv; bias = bv; C = g_V; }
    gemm_mma_body(y, W, bias, C);
}

__global__ __launch_bounds__(256, 2)
void gemm_out_kernel(const float* __restrict__ Wo,
                     const float* __restrict__ bo,
                     float* __restrict__ out)
{
    gemm_mma_body(g_O, Wo, bo, out);
}

// ---------------------------------------------------------------------------
// Flash attention on mma.sync (FA2 style), split-fp32 everywhere.
// Block: 128 q-rows x (head, batch).  8 warps, each owns 16 q-rows.
// K-tile 64.  S = QK^T (k=d), softmax on fragments, O += P.V (k=j).
// ---------------------------------------------------------------------------
__global__ __launch_bounds__(256, 2)
void attn_mma_kernel()
{
    extern __shared__ __align__(16) uint16_t smA[];
    uint16_t* Qh = smA;
    uint16_t* Ql = Qh + 128 * AST;
    uint16_t* Kh = Ql + 128 * AST;
    uint16_t* Kl = Kh + 64 * AST;
    uint16_t* Vh = Kl + 64 * AST;
    uint16_t* Vl = Vh + 64 * AST;

    const int tid = threadIdx.x;
    const int lane = tid & 31;
    const int wid = tid >> 5;            // warp owns q rows wid*16..+15
    const int g = lane >> 2;
    const int t4 = lane & 3;
    const int q0 = blockIdx.x * 128;
    const int h = blockIdx.y;
    const int b = blockIdx.z;

    const float* Qg = g_Q + (size_t)(b * Nn) * DM + h * Dh;
    const float* Kg = g_K + (size_t)(b * Nn) * DM + h * Dh;
    const float* Vg = g_V + (size_t)(b * Nn) * DM + h * Dh;

    const float SCALE = 0.125f;   // folded into Q at conversion

    // Load Q tile (128x64), scale, split hi/lo. 2048 float4, 8/thread.
#pragma unroll
    for (int i = 0; i < 8; i++) {
        const int f = tid + i * 256;
        const int r = f >> 4;
        const int c4 = f & 15;
        float4 v = *reinterpret_cast<const float4*>(
            Qg + (size_t)(q0 + r) * DM + c4 * 4);
        v.x *= SCALE; v.y *= SCALE; v.z *= SCALE; v.w *= SCALE;
        uint32_t h0 = pack_bf16x2(v.y, v.x);
        uint32_t h1 = pack_bf16x2(v.w, v.z);
        uint32_t l0 = pack_bf16x2(v.y - bf_hi(h0), v.x - bf_lo(h0));
        uint32_t l1 = pack_bf16x2(v.w - bf_hi(h1), v.z - bf_lo(h1));
        *reinterpret_cast<uint2*>(&Qh[r * AST + c4 * 4]) = make_uint2(h0, h1);
        *reinterpret_cast<uint2*>(&Ql[r * AST + c4 * 4]) = make_uint2(l0, l1);
    }

    // ldmatrix base addresses
    const uint32_t qAH = smem_u32(Qh) +
        (uint32_t)(((wid * 16 + (lane & 15)) * AST + (lane >> 4) * 8) * 2);
    const uint32_t qAL = smem_u32(Ql) +
        (uint32_t)(((wid * 16 + (lane & 15)) * AST + (lane >> 4) * 8) * 2);
    // B-frag x4 addressing (K non-trans and V trans share the same form):
    // row = base + ((lane>>3)&1)*8 + (lane&7), col = (lane>>4)*8
    const int bRow = ((lane >> 3) & 1) * 8 + (lane & 7);
    const int bCol = (lane >> 4) * 8;
    const uint32_t kBH = smem_u32(Kh) + (uint32_t)((bRow * AST + bCol) * 2);
    const uint32_t kBL = smem_u32(Kl) + (uint32_t)((bRow * AST + bCol) * 2);
    const uint32_t vBH = smem_u32(Vh) + (uint32_t)((bRow * AST + bCol) * 2);
    const uint32_t vBL = smem_u32(Vl) + (uint32_t)((bRow * AST + bCol) * 2);

    float oa[8][4];
#pragma unroll
    for (int t = 0; t < 8; t++)
#pragma unroll
        for (int r = 0; r < 4; r++) oa[t][r] = 0.0f;
    float mr[2] = {-1e30f, -1e30f};
    float lr[2] = {0.0f, 0.0f};

    for (int kt = 0; kt < Nn / 64; kt++) {
        __syncthreads();   // previous tile fully consumed
        const int k0g = kt * 64;
        // Load K,V (64x64 each), split hi/lo. 1024 float4 each, 4/thread each.
#pragma unroll
        for (int i = 0; i < 4; i++) {
            const int f = tid + i * 256;
            const int r = f >> 4;
            const int c4 = f & 15;
            float4 kv = *reinterpret_cast<const float4*>(
                Kg + (size_t)(k0g + r) * DM + c4 * 4);
            uint32_t h0 = pack_bf16x2(kv.y, kv.x);
            uint32_t h1 = pack_bf16x2(kv.w, kv.z);
            uint32_t l0 = pack_bf16x2(kv.y - bf_hi(h0), kv.x - bf_lo(h0));
            uint32_t l1 = pack_bf16x2(kv.w - bf_hi(h1), kv.z - bf_lo(h1));
            *reinterpret_cast<uint2*>(&Kh[r * AST + c4 * 4]) = make_uint2(h0, h1);
            *reinterpret_cast<uint2*>(&Kl[r * AST + c4 * 4]) = make_uint2(l0, l1);

            float4 vv = *reinterpret_cast<const float4*>(
                Vg + (size_t)(k0g + r) * DM + c4 * 4);
            uint32_t vh0 = pack_bf16x2(vv.y, vv.x);
            uint32_t vh1 = pack_bf16x2(vv.w, vv.z);
            uint32_t vl0 = pack_bf16x2(vv.y - bf_hi(vh0), vv.x - bf_lo(vh0));
            uint32_t vl1 = pack_bf16x2(vv.w - bf_hi(vh1), vv.z - bf_lo(vh1));
            *reinterpret_cast<uint2*>(&Vh[r * AST + c4 * 4]) = make_uint2(vh0, vh1);
            *reinterpret_cast<uint2*>(&Vl[r * AST + c4 * 4]) = make_uint2(vl0, vl1);
        }
        __syncthreads();

        // ---- S = Q.K^T : m16 x n64, k=d=64 ----
        float sa[8][4];
#pragma unroll
        for (int t = 0; t < 8; t++)
#pragma unroll
            for (int r = 0; r < 4; r++) sa[t][r] = 0.0f;

#pragma unroll
        for (int kk = 0; kk < 4; kk++) {
            uint32_t aH[4], aL[4];
            ldsm_x4(aH, qAH + kk * 32);     // +16 bf16 cols
            ldsm_x4(aL, qAL + kk * 32);
#pragma unroll
            for (int n2 = 0; n2 < 4; n2++) {
                uint32_t bH[4], bL[4];
                ldsm_x4(bH, kBH + (uint32_t)((n2 * 16 * AST + kk * 16) * 2));
                ldsm_x4(bL, kBL + (uint32_t)((n2 * 16 * AST + kk * 16) * 2));
                // x4 non-trans: {m0,m2} = tile n2*2 (b0,b1); {m1,m3} = tile n2*2+1
                uint32_t b0h[2] = {bH[0], bH[2]}, b1h[2] = {bH[1], bH[3]};
                uint32_t b0l[2] = {bL[0], bL[2]}, b1l[2] = {bL[1], bL[3]};
                mma16816(sa[n2 * 2], aH, b0h);
                mma16816(sa[n2 * 2], aH, b0l);
                mma16816(sa[n2 * 2], aL, b0h);
                mma16816(sa[n2 * 2 + 1], aH, b1h);
                mma16816(sa[n2 * 2 + 1], aH, b1l);
                mma16816(sa[n2 * 2 + 1], aL, b1h);
            }
        }

        // ---- online softmax on fragments (rows g and g+8) ----
        float tm0 = -1e30f, tm1 = -1e30f;
#pragma unroll
        for (int t = 0; t < 8; t++) {
            tm0 = fmaxf(tm0, fmaxf(sa[t][0], sa[t][1]));
            tm1 = fmaxf(tm1, fmaxf(sa[t][2], sa[t][3]));
        }
        tm0 = fmaxf(tm0, __shfl_xor_sync(0xffffffffu, tm0, 1));
        tm0 = fmaxf(tm0, __shfl_xor_sync(0xffffffffu, tm0, 2));
        tm1 = fmaxf(tm1, __shfl_xor_sync(0xffffffffu, tm1, 1));
        tm1 = fmaxf(tm1, __shfl_xor_sync(0xffffffffu, tm1, 2));
        const float nm0 = fmaxf(mr[0], tm0);
        const float nm1 = fmaxf(mr[1], tm1);
        const float cr0 = __expf(mr[0] - nm0);
        const float cr1 = __expf(mr[1] - nm1);
        float ps0 = 0.0f, ps1 = 0.0f;
#pragma unroll
        for (int t = 0; t < 8; t++) {
            sa[t][0] = __expf(sa[t][0] - nm0); ps0 += sa[t][0];
            sa[t][1] = __expf(sa[t][1] - nm0); ps0 += sa[t][1];
            sa[t][2] = __expf(sa[t][2] - nm1); ps1 += sa[t][2];
            sa[t][3] = __expf(sa[t][3] - nm1); ps1 += sa[t][3];
        }
        ps0 += __shfl_xor_sync(0xffffffffu, ps0, 1);
        ps0 += __shfl_xor_sync(0xffffffffu, ps0, 2);
        ps1 += __shfl_xor_sync(0xffffffffu, ps1, 1);
        ps1 += __shfl_xor_sync(0xffffffffu, ps1, 2);
        lr[0] = lr[0] * cr0 + ps0;  mr[0] = nm0;
        lr[1] = lr[1] * cr1 + ps1;  mr[1] = nm1;
#pragma unroll
        for (int t = 0; t < 8; t++) {
            oa[t][0] *= cr0; oa[t][1] *= cr0;
            oa[t][2] *= cr1; oa[t][3] *= cr1;
        }

        // ---- O += P.V : m16 x n64(d), k=j=64 ----
#pragma unroll
        for (int kk = 0; kk < 4; kk++) {
            // repack S-tiles 2kk, 2kk+1 into A fragment (+ exact lo residual)
            const float* s0 = sa[2 * kk];
            const float* s1 = sa[2 * kk + 1];
            uint32_t pH[4], pL[4];
            pH[0] = pack_bf16x2(s0[1], s0[0]);
            pL[0] = pack_bf16x2(s0[1] - bf_hi(pH[0]), s0[0] - bf_lo(pH[0]));
            pH[1] = pack_bf16x2(s0[3], s0[2]);
            pL[1] = pack_bf16x2(s0[3] - bf_hi(pH[1]), s0[2] - bf_lo(pH[1]));
            pH[2] = pack_bf16x2(s1[1], s1[0]);
            pL[2] = pack_bf16x2(s1[1] - bf_hi(pH[2]), s1[0] - bf_lo(pH[2]));
            pH[3] = pack_bf16x2(s1[3], s1[2]);
            pL[3] = pack_bf16x2(s1[3] - bf_hi(pH[3]), s1[2] - bf_lo(pH[3]));
#pragma unroll
            for (int d2 = 0; d2 < 4; d2++) {
                uint32_t bH[4], bL[4];
                ldsm_x4_t(bH, vBH + (uint32_t)((kk * 16 * AST + d2 * 16) * 2));
                ldsm_x4_t(bL, vBL + (uint32_t)((kk * 16 * AST + d2 * 16) * 2));
                // x4 trans: {m0,m1} = tile d2*2 (b0,b1); {m2,m3} = tile d2*2+1
                uint32_t b0h[2] = {bH[0], bH[1]}, b1h[2] = {bH[2], bH[3]};
                uint32_t b0l[2] = {bL[0], bL[1]}, b1l[2] = {bL[2], bL[3]};
                mma16816(oa[d2 * 2], pH, b0h);
                mma16816(oa[d2 * 2], pH, b0l);
                mma16816(oa[d2 * 2], pL, b0h);
                mma16816(oa[d2 * 2 + 1], pH, b1h);
                mma16816(oa[d2 * 2 + 1], pH, b1l);
                mma16816(oa[d2 * 2 + 1], pL, b1h);
            }
        }
    }

    // normalize and write O (b,n,h,d)
    const float inv0 = 1.0f / lr[0];
    const float inv1 = 1.0f / lr[1];
    float* Og = g_O + (size_t)(b * Nn) * DM + h * Dh;
    const int row0 = q0 + wid * 16 + g;
#pragma unroll
    for (int t = 0; t < 8; t++) {
        const int col = t * 8 + t4 * 2;
        float2 o0 = make_float2(oa[t][0] * inv0, oa[t][1] * inv0);
        float2 o1 = make_float2(oa[t][2] * inv1, oa[t][3] * inv1);
        *reinterpret_cast<float2*>(Og + (size_t)row0 * DM + col) = o0;
        *reinterpret_cast<float2*>(Og + (size_t)(row0 + 8) * DM + col) = o1;
    }
}

// ---------------------------------------------------------------------------
// Launch
// ---------------------------------------------------------------------------
extern "C" void kernel_launch(void* const* d_in, const int* in_sizes, int n_in,
                              void* d_out, int out_size)
{
    const float* y  = (const float*)d_in[0];
    const float* Wq = (const float*)d_in[1];
    const float* bq = (const float*)d_in[2];
    const float* Wk = (const float*)d_in[3];
    const float* bk = (const float*)d_in[4];
    const float* Wv = (const float*)d_in[5];
    const float* bv = (const float*)d_in[6];
    const float* Wo = (const float*)d_in[7];
    const float* bo = (const float*)d_in[8];
    float* out = (float*)d_out;

    cudaFuncSetAttribute(attn_mma_kernel,
                         cudaFuncAttributeMaxDynamicSharedMemorySize, ATTN_SMEM);

    // 1) Q/K/V projections (mma.sync split-bf16).
    dim3 gq(DM / 128, Mrows / 128, 3);   // (8, 32, 3)
    gemm_qkv_kernel<<<gq, 256>>>(y, Wq, bq, Wk, bk, Wv, bv);

    // 2) Flash attention (mma.sync split-bf16).
    dim3 ga(Nn / 128, Hh, Bb);           // (16, 16, 2)
    attn_mma_kernel<<<ga, 256, ATTN_SMEM>>>();

    // 3) Output projection -> d_out.
    dim3 go(DM / 128, Mrows / 128);      // (8, 32)
    gemm_out_kernel<<<go, 256>>>(Wo, bo, out);
}